// round 14
// baseline (speedup 1.0000x reference)
#include <cuda_runtime.h>
#include <cstddef>

#define NUQ 500000
#define NIQ 100000
#define FDIM 300
#define DQ 64
#define NE 2000000
#define NL 1000000
#define NTOT (NUQ + NIQ)      // 600000
#define NADJ (2 * NE)         // 4000000
#define NBLK 293              // ceil(NTOT / 2048)

typedef unsigned long long u64;

// ---------------- device scratch (no runtime allocation allowed) ----------------
__device__ __align__(16) float g_xu[(size_t)NUQ * DQ];     // user features (in-place per layer)
__device__ __align__(16) float g_xi[(size_t)NIQ * DQ];     // item features (in-place per layer)
__device__ __align__(16) float g_agg_u[(size_t)NUQ * DQ];  // mean of item msgs at users
__device__ __align__(16) float g_agg_i[(size_t)NIQ * DQ];  // mean of user msgs at items
__device__ int  g_cnt[NTOT];      // degrees: users [0,NU), items [NU,NU+NI)
__device__ int  g_off[NTOT];      // exclusive scan of g_cnt (scan scratch)
__device__ int  g_cur[NTOT];      // fill cursors
__device__ int2 g_meta[NTOT];     // {offset, count} fused for one-load access
__device__ int  g_adj[NADJ];      // user buckets hold item ids; item buckets hold user ids
__device__ int  g_bsum[NBLK];

// ---------------- helpers ----------------
__device__ __forceinline__ void fma2(u64& acc, u64 a, u64 b) {
    asm("fma.rn.f32x2 %0, %1, %2, %0;" : "+l"(acc) : "l"(a), "l"(b));
}
__device__ __forceinline__ u64 pack2(float x, float y) {
    u64 r; asm("mov.b64 %0, {%1, %2};" : "=l"(r) : "f"(x), "f"(y)); return r;
}
__device__ __forceinline__ float2 unpack2(u64 v) {
    float2 r; asm("mov.b64 {%0, %1}, %2;" : "=f"(r.x), "=f"(r.y) : "l"(v)); return r;
}
__device__ __forceinline__ int clampi(int v, int lo, int hi) {
    return min(max(v, lo), hi);
}
__device__ __forceinline__ int warp_incl_scan(int v) {
    int lane = threadIdx.x & 31;
#pragma unroll
    for (int d = 1; d < 32; d <<= 1) {
        int n = __shfl_up_sync(0xffffffffu, v, d);
        if (lane >= d) v += n;
    }
    return v;
}

// ---------------- CSR build ----------------
__global__ void k_zero_cnt() {
    for (int i = blockIdx.x * blockDim.x + threadIdx.x; i < NTOT;
         i += gridDim.x * blockDim.x) g_cnt[i] = 0;
}

__global__ void k_count(const int* __restrict__ esrc, const int* __restrict__ edst) {
    int e = blockIdx.x * blockDim.x + threadIdx.x;
    if (e >= NE) return;
    int u  = clampi(esrc[e], 0, NUQ - 1);
    int it = clampi(edst[e], 0, NIQ - 1);
    atomicAdd(&g_cnt[u], 1);
    atomicAdd(&g_cnt[NUQ + it], 1);
}

// 3-phase exclusive scan of g_cnt -> g_off (chunk = 2048 per block)
__global__ void __launch_bounds__(1024) k_scan1() {
    __shared__ int wsum[32];
    int t = threadIdx.x, lane = t & 31, w = t >> 5;
    int i0 = blockIdx.x * 2048 + 2 * t;
    int a = (i0 < NTOT)     ? g_cnt[i0]     : 0;
    int b = (i0 + 1 < NTOT) ? g_cnt[i0 + 1] : 0;
    int s = a + b;
    int incl = warp_incl_scan(s);
    if (lane == 31) wsum[w] = incl;
    __syncthreads();
    if (w == 0) {
        int ws = wsum[lane];
        int wincl = warp_incl_scan(ws);
        wsum[lane] = wincl - ws;                       // exclusive warp offset
        if (lane == 31) g_bsum[blockIdx.x] = wincl;    // block total
    }
    __syncthreads();
    int excl = incl - s + wsum[w];
    if (i0 < NTOT)     g_off[i0]     = excl;
    if (i0 + 1 < NTOT) g_off[i0 + 1] = excl + a;
}

__global__ void __launch_bounds__(512) k_scan2() {   // scans NBLK(<=512) block sums
    __shared__ int wsum[16];
    int t = threadIdx.x, lane = t & 31, w = t >> 5;
    int v0 = (t < NBLK) ? g_bsum[t] : 0;
    int incl = warp_incl_scan(v0);
    if (lane == 31) wsum[w] = incl;
    __syncthreads();
    if (w == 0 && lane < 16) {
        int ws = wsum[lane];
        int wincl = ws;
#pragma unroll
        for (int d = 1; d < 16; d <<= 1) {
            int n = __shfl_up_sync(0x0000ffffu, wincl, d, 16);
            if (lane >= d) wincl += n;
        }
        wsum[lane] = wincl - ws;
    }
    __syncthreads();
    if (t < NBLK) g_bsum[t] = incl - v0 + wsum[w];
}

__global__ void __launch_bounds__(1024) k_scan3() {
    int add = g_bsum[blockIdx.x];
    int i = blockIdx.x * 2048 + threadIdx.x;
#pragma unroll
    for (int r = 0; r < 2; r++, i += 1024) {
        if (i < NTOT) {
            int o = g_off[i] + add;
            g_cur[i]  = o;
            g_meta[i] = make_int2(o, g_cnt[i]);
        }
    }
}

__global__ void k_fill(const int* __restrict__ esrc, const int* __restrict__ edst) {
    int e = blockIdx.x * blockDim.x + threadIdx.x;
    if (e >= NE) return;
    int u  = clampi(esrc[e], 0, NUQ - 1);
    int it = clampi(edst[e], 0, NIQ - 1);
    int p1 = clampi(atomicAdd(&g_cur[u], 1),        0, NADJ - 1);
    int p2 = clampi(atomicAdd(&g_cur[NUQ + it], 1), 0, NADJ - 1);
    g_adj[p1] = it;   // user bucket: neighbor item ids
    g_adj[p2] = u;    // item bucket: neighbor user ids
}

// ---------------- input layers ----------------
// x_user = user_emb_w[user_node_id]  (faithful gather; one float4 per thread)
__global__ void k_gather_user(const float4* __restrict__ emb, const int* __restrict__ uid) {
    size_t i = blockIdx.x * (size_t)blockDim.x + threadIdx.x;  // over NUQ*16 float4s
    int row = (int)(i >> 4);
    int c = (int)(i & 15);
    int id = clampi(uid[row], 0, NUQ - 1);
    ((float4*)g_xu)[i] = emb[(size_t)id * 16 + c];
}

// g_xi = item_x @ W + b. Warp computes 8 rows; weights staged in shared as
// float4-of-4-consecutive-k so each lane does LDS.128; x read as broadcast
// float4 (K split 160/140 to keep 16B alignment). Per 4-k group: 8 wf weights
// + 8 wf x vs 16 fma-issue cycles -> balanced at the fma2 floor.
__global__ void __launch_bounds__(256) k_itemlin(const float* __restrict__ x,
                                                 const float* __restrict__ W,
                                                 const float* __restrict__ b) {
    __shared__ __align__(16) float4 ws4[40 * 64];   // max chunk: 40 4-k groups x 64 cols
    int tid = threadIdx.x, lane = tid & 31, warp = tid >> 5;
    int row0 = (blockIdx.x * 8 + warp) * 8;

    const float* xr[8];
#pragma unroll
    for (int r = 0; r < 8; r++)
        xr[r] = x + (size_t)clampi(row0 + r, 0, NIQ - 1) * FDIM;

    u64 acc[8][2];
#pragma unroll
    for (int r = 0; r < 8; r++) { acc[r][0] = 0ull; acc[r][1] = 0ull; }

#pragma unroll
    for (int chunk = 0; chunk < 2; chunk++) {
        const int n4 = chunk ? 35 : 40;     // 4-k groups in this chunk
        const int k0 = chunk ? 160 : 0;
        if (chunk) __syncthreads();
        for (int idx = tid; idx < n4 * 64; idx += 256) {
            int pq = idx >> 6, d = idx & 63;
            int k = k0 + 4 * pq;
            ws4[idx] = make_float4(W[(size_t)k * DQ + d],       W[(size_t)(k + 1) * DQ + d],
                                   W[(size_t)(k + 2) * DQ + d], W[(size_t)(k + 3) * DQ + d]);
        }
        __syncthreads();
#pragma unroll 2
        for (int pq = 0; pq < n4; pq++) {
            float4 wA = ws4[pq * 64 + lane];
            float4 wB = ws4[pq * 64 + lane + 32];
            u64 wA01 = pack2(wA.x, wA.y), wA23 = pack2(wA.z, wA.w);
            u64 wB01 = pack2(wB.x, wB.y), wB23 = pack2(wB.z, wB.w);
#pragma unroll
            for (int r = 0; r < 8; r++) {
                float4 xv = *(const float4*)(xr[r] + k0 + 4 * pq);
                u64 x01 = pack2(xv.x, xv.y), x23 = pack2(xv.z, xv.w);
                fma2(acc[r][0], x01, wA01);
                fma2(acc[r][0], x23, wA23);
                fma2(acc[r][1], x01, wB01);
                fma2(acc[r][1], x23, wB23);
            }
        }
    }
    float b0 = b[lane], b1 = b[lane + 32];
#pragma unroll
    for (int r = 0; r < 8; r++) {
        if (row0 + r < NIQ) {
            float2 a0 = unpack2(acc[r][0]), a1 = unpack2(acc[r][1]);
            g_xi[(size_t)(row0 + r) * DQ + lane]      = b0 + a0.x + a0.y;
            g_xi[(size_t)(row0 + r) * DQ + lane + 32] = b1 + a1.x + a1.y;
        }
    }
}

// ---------------- aggregation (gather over CSR): agg = mean of neighbor rows --
// float4 lanes, 2 neighbors per warp-step, 4 row-loads in flight in the
// unrolled path, fused {off,cnt} metadata load.
template <bool USER>
__global__ void __launch_bounds__(256) k_agg() {
    int gw = (blockIdx.x * blockDim.x + threadIdx.x) >> 5;
    int lane = threadIdx.x & 31;
    int nwarp = (gridDim.x * blockDim.x) >> 5;
    const int n = USER ? NUQ : NIQ;
    const float* __restrict__ src = USER ? g_xi : g_xu;
    float* __restrict__ dst       = USER ? g_agg_u : g_agg_i;
    const int base = USER ? 0 : NUQ;
    int half = lane >> 4;       // 0: even neighbor, 1: odd neighbor
    int c4 = lane & 15;         // float4 index within the 64-float row

    for (int node = gw; node < n; node += nwarp) {
        int2 oc = g_meta[base + node];
        int start = oc.x, len = oc.y;
        float4 accA = make_float4(0.f, 0.f, 0.f, 0.f);
        float4 accB = accA, accC = accA, accD = accA;
        for (int jb = 0; jb < len; jb += 32) {
            int nb = 0;
            if (jb + lane < len) nb = g_adj[start + jb + lane];
            int m = min(32, len - jb);
            int k = 0;
            for (; k + 8 <= m; k += 8) {
                int i0 = __shfl_sync(0xffffffffu, nb, k);
                int i1 = __shfl_sync(0xffffffffu, nb, k + 1);
                int i2 = __shfl_sync(0xffffffffu, nb, k + 2);
                int i3 = __shfl_sync(0xffffffffu, nb, k + 3);
                int i4 = __shfl_sync(0xffffffffu, nb, k + 4);
                int i5 = __shfl_sync(0xffffffffu, nb, k + 5);
                int i6 = __shfl_sync(0xffffffffu, nb, k + 6);
                int i7 = __shfl_sync(0xffffffffu, nb, k + 7);
                int idA = half ? i1 : i0;
                int idB = half ? i3 : i2;
                int idC = half ? i5 : i4;
                int idD = half ? i7 : i6;
                float4 vA = *(const float4*)(src + (size_t)idA * DQ + c4 * 4);
                float4 vB = *(const float4*)(src + (size_t)idB * DQ + c4 * 4);
                float4 vC = *(const float4*)(src + (size_t)idC * DQ + c4 * 4);
                float4 vD = *(const float4*)(src + (size_t)idD * DQ + c4 * 4);
                accA.x += vA.x; accA.y += vA.y; accA.z += vA.z; accA.w += vA.w;
                accB.x += vB.x; accB.y += vB.y; accB.z += vB.z; accB.w += vB.w;
                accC.x += vC.x; accC.y += vC.y; accC.z += vC.z; accC.w += vC.w;
                accD.x += vD.x; accD.y += vD.y; accD.z += vD.z; accD.w += vD.w;
            }
            for (; k + 2 <= m; k += 2) {
                int i0 = __shfl_sync(0xffffffffu, nb, k);
                int i1 = __shfl_sync(0xffffffffu, nb, k + 1);
                int id = half ? i1 : i0;
                float4 v = *(const float4*)(src + (size_t)id * DQ + c4 * 4);
                accA.x += v.x; accA.y += v.y; accA.z += v.z; accA.w += v.w;
            }
            if (k < m) {   // single leftover: only half 0 contributes
                int i0 = __shfl_sync(0xffffffffu, nb, k);
                float4 v = *(const float4*)(src + (size_t)i0 * DQ + c4 * 4);
                if (!half) {
                    accA.x += v.x; accA.y += v.y; accA.z += v.z; accA.w += v.w;
                }
            }
        }
        float4 a = make_float4((accA.x + accB.x) + (accC.x + accD.x),
                               (accA.y + accB.y) + (accC.y + accD.y),
                               (accA.z + accB.z) + (accC.z + accD.z),
                               (accA.w + accB.w) + (accC.w + accD.w));
        a.x += __shfl_down_sync(0xffffffffu, a.x, 16);
        a.y += __shfl_down_sync(0xffffffffu, a.y, 16);
        a.z += __shfl_down_sync(0xffffffffu, a.z, 16);
        a.w += __shfl_down_sync(0xffffffffu, a.w, 16);
        if (half == 0) {
            float inv = 1.0f / (float)max(len, 1);
            a.x *= inv; a.y *= inv; a.z *= inv; a.w *= inv;
            *(float4*)(dst + (size_t)node * DQ + c4 * 4) = a;
        }
    }
}

// ---------------- node transform: x = relu?( agg@Wl + b + x@Wr ) -------------
// Warp per 8-row group; lane owns output cols {lane, lane+32}. 8-row blocking
// halves the weight-LDS wavefront share (16 wf/q over 8 rows); weights staged
// as float4-of-4k for LDS.128. Per q: 32 wf == 32 fma-issue cycles -> balanced
// at the fma2 floor.
template <bool RELU, bool USER>
__global__ void __launch_bounds__(256) k_transform(const float* __restrict__ Wl,
                                                   const float* __restrict__ bias,
                                                   const float* __restrict__ Wr) {
    __shared__ __align__(16) float4 wl4[16 * 64];
    __shared__ __align__(16) float4 wr4[16 * 64];
    const float* agg = USER ? g_agg_u : g_agg_i;
    float*       x   = USER ? g_xu : g_xi;
    const int    ngrp = (USER ? NUQ : NIQ) / 8;   // both divisible by 8

    int tid = threadIdx.x, lane = tid & 31, warp = tid >> 5;
    for (int idx = tid; idx < 16 * 64; idx += 256) {
        int q = idx >> 6, d = idx & 63;
        int k = 4 * q;
        wl4[idx] = make_float4(Wl[(size_t)k * DQ + d],       Wl[(size_t)(k + 1) * DQ + d],
                               Wl[(size_t)(k + 2) * DQ + d], Wl[(size_t)(k + 3) * DQ + d]);
        wr4[idx] = make_float4(Wr[(size_t)k * DQ + d],       Wr[(size_t)(k + 1) * DQ + d],
                               Wr[(size_t)(k + 2) * DQ + d], Wr[(size_t)(k + 3) * DQ + d]);
    }
    float b0 = bias[lane], b1 = bias[lane + 32];
    __syncthreads();

    for (int g = blockIdx.x * 8 + warp; g < ngrp; g += gridDim.x * 8) {
        int row0 = g * 8;
        const float* arow = agg + (size_t)row0 * DQ;
        const float* xrow = x + (size_t)row0 * DQ;
        u64 acc[8][2];
#pragma unroll
        for (int r = 0; r < 8; r++) { acc[r][0] = 0ull; acc[r][1] = 0ull; }

#pragma unroll 2
        for (int q = 0; q < 16; q++) {
            float4 wlA = wl4[q * 64 + lane];
            float4 wlB = wl4[q * 64 + lane + 32];
            float4 wrA = wr4[q * 64 + lane];
            float4 wrB = wr4[q * 64 + lane + 32];
            u64 wlA01 = pack2(wlA.x, wlA.y), wlA23 = pack2(wlA.z, wlA.w);
            u64 wlB01 = pack2(wlB.x, wlB.y), wlB23 = pack2(wlB.z, wlB.w);
            u64 wrA01 = pack2(wrA.x, wrA.y), wrA23 = pack2(wrA.z, wrA.w);
            u64 wrB01 = pack2(wrB.x, wrB.y), wrB23 = pack2(wrB.z, wrB.w);
#pragma unroll
            for (int r = 0; r < 8; r++) {
                float4 av = *(const float4*)(arow + (size_t)r * DQ + 4 * q);
                float4 xv = *(const float4*)(xrow + (size_t)r * DQ + 4 * q);
                u64 a01 = pack2(av.x, av.y), a23 = pack2(av.z, av.w);
                u64 x01 = pack2(xv.x, xv.y), x23 = pack2(xv.z, xv.w);
                fma2(acc[r][0], a01, wlA01);
                fma2(acc[r][0], a23, wlA23);
                fma2(acc[r][0], x01, wrA01);
                fma2(acc[r][0], x23, wrA23);
                fma2(acc[r][1], a01, wlB01);
                fma2(acc[r][1], a23, wlB23);
                fma2(acc[r][1], x01, wrB01);
                fma2(acc[r][1], x23, wrB23);
            }
        }
#pragma unroll
        for (int r = 0; r < 8; r++) {
            float2 A0 = unpack2(acc[r][0]), A1 = unpack2(acc[r][1]);
            float o0 = b0 + A0.x + A0.y;
            float o1 = b1 + A1.x + A1.y;
            if (RELU) { o0 = fmaxf(o0, 0.f); o1 = fmaxf(o1, 0.f); }
            x[(size_t)(row0 + r) * DQ + lane]      = o0;
            x[(size_t)(row0 + r) * DQ + lane + 32] = o1;
        }
    }
}

// ---------------- predictor: out[e] = dot(hu[lsrc[e]], hi[ldst[e]]) ----------
__global__ void k_dot(const int* __restrict__ lsrc, const int* __restrict__ ldst,
                      float* __restrict__ out) {
    int t = blockIdx.x * blockDim.x + threadIdx.x;
    int e = t >> 3;   // 8 lanes per edge; grid sized exactly
    int c = t & 7;
    int su = clampi(__ldg(&lsrc[e]), 0, NUQ - 1);
    int si = clampi(__ldg(&ldst[e]), 0, NIQ - 1);
    const float4* a = (const float4*)(g_xu + (size_t)su * DQ);
    const float4* b = (const float4*)(g_xi + (size_t)si * DQ);
    float4 a0 = a[2 * c], a1 = a[2 * c + 1];
    float4 b0 = b[2 * c], b1 = b[2 * c + 1];
    float s = a0.x * b0.x;
    s = fmaf(a0.y, b0.y, s); s = fmaf(a0.z, b0.z, s); s = fmaf(a0.w, b0.w, s);
    s = fmaf(a1.x, b1.x, s); s = fmaf(a1.y, b1.y, s);
    s = fmaf(a1.z, b1.z, s); s = fmaf(a1.w, b1.w, s);
    s += __shfl_down_sync(0xffffffffu, s, 4, 8);
    s += __shfl_down_sync(0xffffffffu, s, 2, 8);
    s += __shfl_down_sync(0xffffffffu, s, 1, 8);
    if (c == 0) out[e] = s;
}

// ---------------- launch ----------------
extern "C" void kernel_launch(void* const* d_in, const int* in_sizes, int n_in,
                              void* d_out, int out_size) {
    (void)in_sizes; (void)n_in; (void)out_size;
    const float* user_emb   = (const float*)d_in[0];
    const float* item_x     = (const float*)d_in[1];
    const float* item_lin_w = (const float*)d_in[2];
    const float* item_lin_b = (const float*)d_in[3];
    const float* Wl1_ui = (const float*)d_in[4];
    const float* Wr1_ui = (const float*)d_in[5];
    const float* b1_ui  = (const float*)d_in[6];
    const float* Wl1_iu = (const float*)d_in[7];
    const float* Wr1_iu = (const float*)d_in[8];
    const float* b1_iu  = (const float*)d_in[9];
    const float* Wl2_ui = (const float*)d_in[10];
    const float* Wr2_ui = (const float*)d_in[11];
    const float* b2_ui  = (const float*)d_in[12];
    const float* Wl2_iu = (const float*)d_in[13];
    const float* Wr2_iu = (const float*)d_in[14];
    const float* b2_iu  = (const float*)d_in[15];
    const int* uid  = (const int*)d_in[16];
    const int* esrc = (const int*)d_in[17];
    const int* edst = (const int*)d_in[18];
    const int* lsrc = (const int*)d_in[19];
    const int* ldst = (const int*)d_in[20];
    float* out = (float*)d_out;

    // Launch order note: ncu capture (-s 5 -c 1, after 2 harness launches)
    // profiles MY 4th launch -> keep k_itemlin there to verify this round's fix.
    k_zero_cnt<<<1024, 256>>>();                                       // 0
    k_count<<<(NE + 255) / 256, 256>>>(esrc, edst);                    // 1
    k_gather_user<<<(NUQ * 16) / 256, 256>>>((const float4*)user_emb, uid);  // 2
    k_itemlin<<<(NIQ + 63) / 64, 256>>>(item_x, item_lin_w, item_lin_b);     // 3 <- profiled
    k_scan1<<<NBLK, 1024>>>();
    k_scan2<<<1, 512>>>();
    k_scan3<<<NBLK, 1024>>>();
    k_fill<<<(NE + 255) / 256, 256>>>(esrc, edst);

    // ---- layer 1 (with ReLU) ----
    k_agg<true ><<<1184, 256>>>();   // users <- mean of item rows
    k_agg<false><<<1184, 256>>>();   // items <- mean of user rows
    k_transform<true,  true ><<<888, 256>>>(Wl1_iu, b1_iu, Wr1_iu);
    k_transform<true,  false><<<888, 256>>>(Wl1_ui, b1_ui, Wr1_ui);

    // ---- layer 2 (no ReLU) ----
    k_agg<true ><<<1184, 256>>>();
    k_agg<false><<<1184, 256>>>();
    k_transform<false, true ><<<888, 256>>>(Wl2_iu, b2_iu, Wr2_iu);
    k_transform<false, false><<<888, 256>>>(Wl2_ui, b2_ui, Wr2_ui);

    // ---- predictor ----
    k_dot<<<(NL * 8) / 256, 256>>>(lsrc, ldst, out);
}